// round 11
// baseline (speedup 1.0000x reference)
#include <cuda_runtime.h>
#include <cuda_fp16.h>
#include <cstdint>

#define TPB 256

// ---- fragment-linear fp16 weight buffer ----
// Per (layer, nt, kh, lane): uint4 = (b0 kt=2kh, b1 kt=2kh, b0 kt=2kh+1, b1 kt=2kh+1)
// where b0 = f16x2 (W[k=16kt+2cp][n], W[k=16kt+2cp+1][n]), b1 = k+8, n = nt*8+g.
#define OFF_S0 0        // K=32 (KH=1), N=64: 256
#define OFF_S1 256      // K=64 (KH=2), N=64: 512
#define OFF_S2 768      // K=64, N=16: 128
#define OFF_C0 896      // K=48 permuted (KH=2), N=64: 512
#define OFF_C1 1408     // 512
#define OFF_C2 1920     // 512
#define OFF_C3 2432     // K=64, N=8: 64
#define WU4    2496

__device__ uint4 wbuf[WU4];

__device__ __forceinline__ uint32_t h2pack(float a, float b) {
    __half2 h = __floats2half2_rn(a, b);
    return *(uint32_t*)&h;
}
__device__ __forceinline__ uint32_t h2relu(float a, float b) {
    __half2 h = __floats2half2_rn(a, b);
    h = __hmax2(h, __half2(__float2half_rn(0.f), __float2half_rn(0.f)));
    return *(uint32_t*)&h;
}

__device__ __forceinline__ void mma16(float* d, const uint32_t* a, uint32_t b0, uint32_t b1) {
    asm volatile(
        "mma.sync.aligned.m16n8k16.row.col.f32.f16.f16.f32 "
        "{%0,%1,%2,%3}, {%4,%5,%6,%7}, {%8,%9}, {%0,%1,%2,%3};"
        : "+f"(d[0]), "+f"(d[1]), "+f"(d[2]), "+f"(d[3])
        : "r"(a[0]), "r"(a[1]), "r"(a[2]), "r"(a[3]), "r"(b0), "r"(b1));
}

// ---------------- prep: weights -> fragment-linear fp16 ----------------
__device__ __forceinline__ float wfetch(const float* W, int Nf, int n, int kk, bool c0) {
    if (n >= Nf) return 0.f;
    int src;
    if (c0) {                       // concat layout: [d 0..31, zero@32, geo@33..47]
        if (kk < 32) src = kk;
        else if (kk == 32) return 0.f;
        else src = kk - 1;
        if (src >= 47) return 0.f;
    } else {
        src = kk;
    }
    return W[src * Nf + n];
}

__global__ void prep_kernel(const float* __restrict__ Ws0, const float* __restrict__ Ws1,
                            const float* __restrict__ Ws2, const float* __restrict__ Wc0,
                            const float* __restrict__ Wc1, const float* __restrict__ Wc2,
                            const float* __restrict__ Wc3) {
    int i = blockIdx.x * blockDim.x + threadIdx.x;
    if (i >= WU4) return;
    const float* W; int Kf, Nf, KH, q; bool c0 = false;
    if      (i < 256)  { W = Ws0; Kf = 32; Nf = 64; KH = 1; q = i;        }
    else if (i < 768)  { W = Ws1; Kf = 64; Nf = 64; KH = 2; q = i - 256;  }
    else if (i < 896)  { W = Ws2; Kf = 64; Nf = 16; KH = 2; q = i - 768;  }
    else if (i < 1408) { W = Wc0; Kf = 48; Nf = 64; KH = 2; q = i - 896; c0 = true; }
    else if (i < 1920) { W = Wc1; Kf = 64; Nf = 64; KH = 2; q = i - 1408; }
    else if (i < 2432) { W = Wc2; Kf = 64; Nf = 64; KH = 2; q = i - 1920; }
    else               { W = Wc3; Kf = 64; Nf = 3;  KH = 2; q = i - 2432; }

    int lane = q & 31, t2 = q >> 5;
    int kh = t2 % KH, nt = t2 / KH;
    int g = lane >> 2, cp = lane & 3;
    int n = nt * 8 + g;

    auto pw = [&](int kk) -> float {
        return (kk < Kf) ? wfetch(W, Nf, n, kk, c0) : 0.f;
    };
    int k0 = 16 * (2 * kh) + 2 * cp;
    int k1 = 16 * (2 * kh + 1) + 2 * cp;
    uint4 v;
    v.x = h2pack(pw(k0),     pw(k0 + 1));
    v.y = h2pack(pw(k0 + 8), pw(k0 + 9));
    v.z = h2pack(pw(k1),     pw(k1 + 1));
    v.w = h2pack(pw(k1 + 8), pw(k1 + 9));
    wbuf[i] = v;
}

// ---------------- main kernel (M=16/warp, persistent, pipelined inputs) ----------------

template <int KT, int NT>
__device__ __forceinline__ void layer_mma(const uint32_t (*aR)[4], const uint4* __restrict__ swL,
                                          int lane, float (*acc)[4]) {
    constexpr int KH = (KT + 1) / 2;
    constexpr int NG = (NT < 4) ? NT : 4;
#pragma unroll
    for (int i = 0; i < NT; i++)
#pragma unroll
        for (int qq = 0; qq < 4; qq++) acc[i][qq] = 0.f;

#pragma unroll
    for (int kh = 0; kh < KH; kh++) {
#pragma unroll
        for (int h = 0; h < NT / NG; h++) {
            uint4 wv[NG];
#pragma unroll
            for (int j = 0; j < NG; j++)
                wv[j] = swL[((h * NG + j) * KH + kh) * 32 + lane];
#pragma unroll
            for (int j = 0; j < NG; j++)
                mma16(acc[h * NG + j], aR[2 * kh], wv[j].x, wv[j].y);
            if (2 * kh + 1 < KT) {
#pragma unroll
                for (int j = 0; j < NG; j++)
                    mma16(acc[h * NG + j], aR[2 * kh + 1], wv[j].z, wv[j].w);
            }
        }
    }
}

__device__ __forceinline__ void cvt_relu8(const float (*acc)[4], uint32_t (*aR)[4]) {
#pragma unroll
    for (int nt = 0; nt < 8; nt++) {
        int kt = nt >> 1, hi = (nt & 1) * 2;
        const float* dd = acc[nt];
        aR[kt][hi + 0] = h2relu(dd[0], dd[1]);
        aR[kt][hi + 1] = h2relu(dd[2], dd[3]);
    }
}

// Load one warp's 16 rows of a [N,32] tensor into 2 fp16 k-tiles.
__device__ __forceinline__ void load_in16(uint32_t (*dst)[4], const float* __restrict__ gsrc,
                                          int p0, int g, int cp) {
#pragma unroll
    for (int kt = 0; kt < 2; kt++) {
        const float* ra = gsrc + (size_t)(p0 + g) * 32 + 2 * cp + 16 * kt;
        const float* rb = ra + 8 * 32;
        float2 v0 = *(const float2*)(ra);
        float2 v1 = *(const float2*)(rb);
        float2 v2 = *(const float2*)(ra + 8);
        float2 v3 = *(const float2*)(rb + 8);
        dst[kt][0] = h2pack(v0.x, v0.y);
        dst[kt][1] = h2pack(v1.x, v1.y);
        dst[kt][2] = h2pack(v2.x, v2.y);
        dst[kt][3] = h2pack(v3.x, v3.y);
    }
}

__global__ __launch_bounds__(TPB, 3)
void RadianceFieldGrid_kernel(const float* __restrict__ x,
                              const float* __restrict__ din,
                              float* __restrict__ out, int N, int numTiles) {
    __shared__ uint4 sW[WU4];   // 39.9 KB

    const int t    = threadIdx.x;
    const int lane = t & 31;
    const int w    = t >> 5;
    const int g    = lane >> 2;
    const int cp   = lane & 3;

    for (int i = t; i < WU4; i += TPB) sW[i] = wbuf[i];
    __syncthreads();

    uint32_t aR[4][4];
    uint32_t xn[2][4];   // prefetched x (next tile)
    uint32_t dn[2][4];   // prefetched d (next tile)
    float acc[8][4];

    int tile = blockIdx.x;
    if (tile < numTiles) {
        load_in16(xn, x,   tile * 128 + w * 16, g, cp);
        load_in16(dn, din, tile * 128 + w * 16, g, cp);
    }

    while (tile < numTiles) {
        const int p0   = tile * 128 + w * 16;
        const int next = tile + gridDim.x;

        // ---- sigma net: consume prefetched x ----
#pragma unroll
        for (int kt = 0; kt < 2; kt++)
#pragma unroll
            for (int j = 0; j < 4; j++)
                aR[kt][j] = xn[kt][j];

        layer_mma<2, 8>(aR, sW + OFF_S0, lane, acc);
        cvt_relu8(acc, aR);
        layer_mma<4, 8>(aR, sW + OFF_S1, lane, acc);
        cvt_relu8(acc, aR);
        layer_mma<4, 2>(aR, sW + OFF_S2, lane, acc);   // acc[0]=cols0-7, acc[1]=cols8-15

        // sigma = relu(col 0) -> out[3N + p]
        if (cp == 0) {
            out[(size_t)3 * N + p0 + g]     = fmaxf(acc[0][0], 0.f);
            out[(size_t)3 * N + p0 + g + 8] = fmaxf(acc[0][2], 0.f);
        }

        // color A: k-tiles 0,1 = prefetched d, k-tile 2 = relu(L2 D-frags)
        aR[2][0] = h2relu(acc[0][0], acc[0][1]);
        aR[2][1] = h2relu(acc[0][2], acc[0][3]);
        aR[2][2] = h2relu(acc[1][0], acc[1][1]);
        aR[2][3] = h2relu(acc[1][2], acc[1][3]);
#pragma unroll
        for (int kt = 0; kt < 2; kt++)
#pragma unroll
            for (int j = 0; j < 4; j++)
                aR[kt][j] = dn[kt][j];

        // ---- color net ----
        layer_mma<3, 8>(aR, sW + OFF_C0, lane, acc);

        // prefetch next tile's inputs; ~3 layers of MMA hide the latency
        if (next < numTiles) {
            load_in16(xn, x,   next * 128 + w * 16, g, cp);
            load_in16(dn, din, next * 128 + w * 16, g, cp);
        }

        cvt_relu8(acc, aR);
        layer_mma<4, 8>(aR, sW + OFF_C1, lane, acc);
        cvt_relu8(acc, aR);
        layer_mma<4, 8>(aR, sW + OFF_C2, lane, acc);
        cvt_relu8(acc, aR);
        layer_mma<4, 1>(aR, sW + OFF_C3, lane, acc);   // acc[0]

        // sigmoid + store color (cols 0..2)
#pragma unroll
        for (int qq = 0; qq < 4; qq++) {
            int c = 2 * cp + (qq & 1);
            if (c < 3) {
                int row = g + 8 * (qq >> 1);
                float v = acc[0][qq];
                out[(size_t)(p0 + row) * 3 + c] = 1.f / (1.f + __expf(-v));
            }
        }

        tile = next;
    }
}

extern "C" void kernel_launch(void* const* d_in, const int* in_sizes, int n_in,
                              void* d_out, int out_size) {
    const float* x   = (const float*)d_in[0];
    const float* din = (const float*)d_in[1];
    const float* Ws0 = (const float*)d_in[2];
    const float* Ws1 = (const float*)d_in[3];
    const float* Ws2 = (const float*)d_in[4];
    const float* Wc0 = (const float*)d_in[5];
    const float* Wc1 = (const float*)d_in[6];
    const float* Wc2 = (const float*)d_in[7];
    const float* Wc3 = (const float*)d_in[8];
    float* out = (float*)d_out;

    int N = in_sizes[0] / 32;   // x is [N, 32]
    int numTiles = N / 128;

    prep_kernel<<<(WU4 + 255) / 256, 256>>>(Ws0, Ws1, Ws2, Wc0, Wc1, Wc2, Wc3);
    RadianceFieldGrid_kernel<<<148 * 3, TPB>>>(x, din, out, N, numTiles);
}

// round 12
// speedup vs baseline: 1.1776x; 1.1776x over previous
#include <cuda_runtime.h>
#include <cuda_fp16.h>
#include <cstdint>

#define TPB 256

// ---- fragment-linear fp16 weight buffer ----
// Per (layer, nt, kh, lane): uint4 = (b0 kt=2kh, b1 kt=2kh, b0 kt=2kh+1, b1 kt=2kh+1)
// where b0 = f16x2 (W[k=16kt+2cp][n], W[k=16kt+2cp+1][n]), b1 = k+8, n = nt*8+g.
#define OFF_S0 0        // K=32 (KH=1), N=64: 256
#define OFF_S1 256      // K=64 (KH=2), N=64: 512
#define OFF_S2 768      // K=64, N=16: 128
#define OFF_C0 896      // K=48 permuted (KH=2), N=64: 512
#define OFF_C1 1408     // 512
#define OFF_C2 1920     // 512
#define OFF_C3 2432     // K=64, N=8: 64
#define WU4    2496

__device__ uint4 wbuf[WU4];

__device__ __forceinline__ uint32_t h2pack(float a, float b) {
    __half2 h = __floats2half2_rn(a, b);
    return *(uint32_t*)&h;
}
__device__ __forceinline__ uint32_t h2relu(float a, float b) {
    __half2 h = __floats2half2_rn(a, b);
    h = __hmax2(h, __half2(__float2half_rn(0.f), __float2half_rn(0.f)));
    return *(uint32_t*)&h;
}

__device__ __forceinline__ void mma16(float* d, const uint32_t* a, uint32_t b0, uint32_t b1) {
    asm volatile(
        "mma.sync.aligned.m16n8k16.row.col.f32.f16.f16.f32 "
        "{%0,%1,%2,%3}, {%4,%5,%6,%7}, {%8,%9}, {%0,%1,%2,%3};"
        : "+f"(d[0]), "+f"(d[1]), "+f"(d[2]), "+f"(d[3])
        : "r"(a[0]), "r"(a[1]), "r"(a[2]), "r"(a[3]), "r"(b0), "r"(b1));
}

// ---------------- prep: weights -> fragment-linear fp16 ----------------
__device__ __forceinline__ float wfetch(const float* W, int Nf, int n, int kk, bool c0) {
    if (n >= Nf) return 0.f;
    int src;
    if (c0) {                       // concat layout: [d 0..31, zero@32, geo@33..47]
        if (kk < 32) src = kk;
        else if (kk == 32) return 0.f;
        else src = kk - 1;
        if (src >= 47) return 0.f;
    } else {
        src = kk;
    }
    return W[src * Nf + n];
}

__global__ void prep_kernel(const float* __restrict__ Ws0, const float* __restrict__ Ws1,
                            const float* __restrict__ Ws2, const float* __restrict__ Wc0,
                            const float* __restrict__ Wc1, const float* __restrict__ Wc2,
                            const float* __restrict__ Wc3) {
    int i = blockIdx.x * blockDim.x + threadIdx.x;
    if (i >= WU4) return;
    const float* W; int Kf, Nf, KH, q; bool c0 = false;
    if      (i < 256)  { W = Ws0; Kf = 32; Nf = 64; KH = 1; q = i;        }
    else if (i < 768)  { W = Ws1; Kf = 64; Nf = 64; KH = 2; q = i - 256;  }
    else if (i < 896)  { W = Ws2; Kf = 64; Nf = 16; KH = 2; q = i - 768;  }
    else if (i < 1408) { W = Wc0; Kf = 48; Nf = 64; KH = 2; q = i - 896; c0 = true; }
    else if (i < 1920) { W = Wc1; Kf = 64; Nf = 64; KH = 2; q = i - 1408; }
    else if (i < 2432) { W = Wc2; Kf = 64; Nf = 64; KH = 2; q = i - 1920; }
    else               { W = Wc3; Kf = 64; Nf = 3;  KH = 2; q = i - 2432; }

    int lane = q & 31, t2 = q >> 5;
    int kh = t2 % KH, nt = t2 / KH;
    int g = lane >> 2, cp = lane & 3;
    int n = nt * 8 + g;

    auto pw = [&](int kk) -> float {
        return (kk < Kf) ? wfetch(W, Nf, n, kk, c0) : 0.f;
    };
    int k0 = 16 * (2 * kh) + 2 * cp;
    int k1 = 16 * (2 * kh + 1) + 2 * cp;
    uint4 v;
    v.x = h2pack(pw(k0),     pw(k0 + 1));
    v.y = h2pack(pw(k0 + 8), pw(k0 + 9));
    v.z = h2pack(pw(k1),     pw(k1 + 1));
    v.w = h2pack(pw(k1 + 8), pw(k1 + 9));
    wbuf[i] = v;
}

// ---------------- main kernel (M=32/warp, persistent CTAs) ----------------

// aR[mt][kt][0..3], acc[mt*NT+nt][0..3]. Each B fragment load feeds 2 m-tiles.
template <int KT, int NT>
__device__ __forceinline__ void layer_mma(const uint32_t (*aR)[4][4], const uint4* __restrict__ swL,
                                          int lane, float (*acc)[4]) {
    constexpr int KH = (KT + 1) / 2;
    constexpr int NG = (NT < 4) ? NT : 4;
#pragma unroll
    for (int i = 0; i < 2 * NT; i++)
#pragma unroll
        for (int qq = 0; qq < 4; qq++) acc[i][qq] = 0.f;

#pragma unroll
    for (int kh = 0; kh < KH; kh++) {
#pragma unroll
        for (int h = 0; h < NT / NG; h++) {
            uint4 wv[NG];
#pragma unroll
            for (int j = 0; j < NG; j++)
                wv[j] = swL[((h * NG + j) * KH + kh) * 32 + lane];
#pragma unroll
            for (int j = 0; j < NG; j++)
#pragma unroll
                for (int mt = 0; mt < 2; mt++)
                    mma16(acc[mt * NT + h * NG + j], aR[mt][2 * kh], wv[j].x, wv[j].y);
            if (2 * kh + 1 < KT) {
#pragma unroll
                for (int j = 0; j < NG; j++)
#pragma unroll
                    for (int mt = 0; mt < 2; mt++)
                        mma16(acc[mt * NT + h * NG + j], aR[mt][2 * kh + 1], wv[j].z, wv[j].w);
            }
        }
    }
}

__device__ __forceinline__ void cvt_relu8(const float (*acc)[4], uint32_t (*aR)[4][4]) {
#pragma unroll
    for (int mt = 0; mt < 2; mt++)
#pragma unroll
        for (int nt = 0; nt < 8; nt++) {
            int kt = nt >> 1, hi = (nt & 1) * 2;
            const float* dd = acc[mt * 8 + nt];
            aR[mt][kt][hi + 0] = h2relu(dd[0], dd[1]);
            aR[mt][kt][hi + 1] = h2relu(dd[2], dd[3]);
        }
}

// Load one warp's 32 rows of a [N,32] tensor into 2 fp16 k-tiles x 2 m-tiles.
template <typename DST>
__device__ __forceinline__ void load_in32(DST&& at, const float* __restrict__ gsrc,
                                          int p0, int g, int cp) {
#pragma unroll
    for (int mt = 0; mt < 2; mt++)
#pragma unroll
        for (int kt = 0; kt < 2; kt++) {
            const float* ra = gsrc + (size_t)(p0 + mt * 16 + g) * 32 + 2 * cp + 16 * kt;
            const float* rb = ra + 8 * 32;
            float2 v0 = *(const float2*)(ra);
            float2 v1 = *(const float2*)(rb);
            float2 v2 = *(const float2*)(ra + 8);
            float2 v3 = *(const float2*)(rb + 8);
            at(mt, kt, 0) = h2pack(v0.x, v0.y);
            at(mt, kt, 1) = h2pack(v1.x, v1.y);
            at(mt, kt, 2) = h2pack(v2.x, v2.y);
            at(mt, kt, 3) = h2pack(v3.x, v3.y);
        }
}

__global__ __launch_bounds__(TPB, 2)
void RadianceFieldGrid_kernel(const float* __restrict__ x,
                              const float* __restrict__ din,
                              float* __restrict__ out, int N, int numTiles) {
    __shared__ uint4 sW[WU4];   // 39.9 KB

    const int t    = threadIdx.x;
    const int lane = t & 31;
    const int w    = t >> 5;
    const int g    = lane >> 2;
    const int cp   = lane & 3;

    // one-time weight copy; persistent CTA amortizes over ~14 tiles
    for (int i = t; i < WU4; i += TPB) sW[i] = wbuf[i];
    __syncthreads();

    uint32_t aR[2][4][4];
    uint32_t dR[2][2][4];
    float acc[16][4];

    for (int tile = blockIdx.x; tile < numTiles; tile += gridDim.x) {
        const int p0 = tile * 256 + w * 32;   // this warp's first point

        // ---- sigma net ----
        load_in32([&](int mt, int kt, int j) -> uint32_t& { return aR[mt][kt][j]; },
                  x, p0, g, cp);
        layer_mma<2, 8>(aR, sW + OFF_S0, lane, acc);
        cvt_relu8(acc, aR);
        layer_mma<4, 8>(aR, sW + OFF_S1, lane, acc);
        // d loads issued here; consumed one layer later (short live range)
        load_in32([&](int mt, int kt, int j) -> uint32_t& { return dR[mt][kt][j]; },
                  din, p0, g, cp);
        cvt_relu8(acc, aR);
        layer_mma<4, 2>(aR, sW + OFF_S2, lane, acc);   // acc[mt*2+nt]

        // sigma = relu(col 0) -> out[3N + p]
        if (cp == 0) {
#pragma unroll
            for (int mt = 0; mt < 2; mt++) {
                out[(size_t)3 * N + p0 + mt * 16 + g]     = fmaxf(acc[mt * 2][0], 0.f);
                out[(size_t)3 * N + p0 + mt * 16 + g + 8] = fmaxf(acc[mt * 2][2], 0.f);
            }
        }

        // color A: k-tiles 0,1 = d, k-tile 2 = relu(L2 D-frags)
#pragma unroll
        for (int mt = 0; mt < 2; mt++) {
            const float* d0 = acc[mt * 2 + 0];
            const float* d1 = acc[mt * 2 + 1];
            aR[mt][2][0] = h2relu(d0[0], d0[1]);
            aR[mt][2][1] = h2relu(d0[2], d0[3]);
            aR[mt][2][2] = h2relu(d1[0], d1[1]);
            aR[mt][2][3] = h2relu(d1[2], d1[3]);
#pragma unroll
            for (int kt = 0; kt < 2; kt++)
#pragma unroll
                for (int j = 0; j < 4; j++)
                    aR[mt][kt][j] = dR[mt][kt][j];
        }

        // ---- color net ----
        layer_mma<3, 8>(aR, sW + OFF_C0, lane, acc);
        cvt_relu8(acc, aR);
        layer_mma<4, 8>(aR, sW + OFF_C1, lane, acc);
        cvt_relu8(acc, aR);
        layer_mma<4, 8>(aR, sW + OFF_C2, lane, acc);
        cvt_relu8(acc, aR);
        layer_mma<4, 1>(aR, sW + OFF_C3, lane, acc);   // acc[mt]

        // sigmoid + store color (cols 0..2)
#pragma unroll
        for (int mt = 0; mt < 2; mt++)
#pragma unroll
            for (int qq = 0; qq < 4; qq++) {
                int c = 2 * cp + (qq & 1);
                if (c < 3) {
                    int row = mt * 16 + g + 8 * (qq >> 1);
                    float v = acc[mt][qq];
                    out[(size_t)(p0 + row) * 3 + c] = 1.f / (1.f + __expf(-v));
                }
            }
    }
}

extern "C" void kernel_launch(void* const* d_in, const int* in_sizes, int n_in,
                              void* d_out, int out_size) {
    const float* x   = (const float*)d_in[0];
    const float* din = (const float*)d_in[1];
    const float* Ws0 = (const float*)d_in[2];
    const float* Ws1 = (const float*)d_in[3];
    const float* Ws2 = (const float*)d_in[4];
    const float* Wc0 = (const float*)d_in[5];
    const float* Wc1 = (const float*)d_in[6];
    const float* Wc2 = (const float*)d_in[7];
    const float* Wc3 = (const float*)d_in[8];
    float* out = (float*)d_out;

    int N = in_sizes[0] / 32;   // x is [N, 32]
    int numTiles = N / 256;     // 256 points per CTA-tile

    prep_kernel<<<(WU4 + 255) / 256, 256>>>(Ws0, Ws1, Ws2, Wc0, Wc1, Wc2, Wc3);
    RadianceFieldGrid_kernel<<<148 * 2, TPB>>>(x, din, out, N, numTiles);
}

// round 13
// speedup vs baseline: 1.7365x; 1.4746x over previous
#include <cuda_runtime.h>
#include <cuda_fp16.h>
#include <cstdint>

#define TPB 256

// ---- fragment-linear fp16 weight buffer ----
// Per (layer, nt, kh, lane): uint4 = (b0 kt=2kh, b1 kt=2kh, b0 kt=2kh+1, b1 kt=2kh+1)
// where b0 = f16x2 (W[k=16kt+2cp][n], W[k=16kt+2cp+1][n]), b1 = k+8, n = nt*8+g.
#define OFF_S0 0        // K=32 (KH=1), N=64: 256
#define OFF_S1 256      // K=64 (KH=2), N=64: 512
#define OFF_S2 768      // K=64, N=16: 128
#define OFF_C0 896      // K=48 permuted (KH=2), N=64: 512
#define OFF_C1 1408     // 512
#define OFF_C2 1920     // 512
#define OFF_C3 2432     // K=64, N=8: 64
#define WU4    2496

__device__ uint4 wbuf[WU4];

__device__ __forceinline__ uint32_t h2pack(float a, float b) {
    __half2 h = __floats2half2_rn(a, b);
    return *(uint32_t*)&h;
}
__device__ __forceinline__ uint32_t h2relu(float a, float b) {
    __half2 h = __floats2half2_rn(a, b);
    h = __hmax2(h, __half2(__float2half_rn(0.f), __float2half_rn(0.f)));
    return *(uint32_t*)&h;
}

__device__ __forceinline__ void mma16(float* d, const uint32_t* a, uint32_t b0, uint32_t b1) {
    asm volatile(
        "mma.sync.aligned.m16n8k16.row.col.f32.f16.f16.f32 "
        "{%0,%1,%2,%3}, {%4,%5,%6,%7}, {%8,%9}, {%0,%1,%2,%3};"
        : "+f"(d[0]), "+f"(d[1]), "+f"(d[2]), "+f"(d[3])
        : "r"(a[0]), "r"(a[1]), "r"(a[2]), "r"(a[3]), "r"(b0), "r"(b1));
}

// ---------------- prep: weights -> fragment-linear fp16 ----------------
__device__ __forceinline__ float wfetch(const float* W, int Nf, int n, int kk, bool c0) {
    if (n >= Nf) return 0.f;
    int src;
    if (c0) {                       // concat layout: [d 0..31, zero@32, geo@33..47]
        if (kk < 32) src = kk;
        else if (kk == 32) return 0.f;
        else src = kk - 1;
        if (src >= 47) return 0.f;
    } else {
        src = kk;
    }
    return W[src * Nf + n];
}

__global__ void prep_kernel(const float* __restrict__ Ws0, const float* __restrict__ Ws1,
                            const float* __restrict__ Ws2, const float* __restrict__ Wc0,
                            const float* __restrict__ Wc1, const float* __restrict__ Wc2,
                            const float* __restrict__ Wc3) {
    int i = blockIdx.x * blockDim.x + threadIdx.x;
    if (i >= WU4) return;
    const float* W; int Kf, Nf, KH, q; bool c0 = false;
    if      (i < 256)  { W = Ws0; Kf = 32; Nf = 64; KH = 1; q = i;        }
    else if (i < 768)  { W = Ws1; Kf = 64; Nf = 64; KH = 2; q = i - 256;  }
    else if (i < 896)  { W = Ws2; Kf = 64; Nf = 16; KH = 2; q = i - 768;  }
    else if (i < 1408) { W = Wc0; Kf = 48; Nf = 64; KH = 2; q = i - 896; c0 = true; }
    else if (i < 1920) { W = Wc1; Kf = 64; Nf = 64; KH = 2; q = i - 1408; }
    else if (i < 2432) { W = Wc2; Kf = 64; Nf = 64; KH = 2; q = i - 1920; }
    else               { W = Wc3; Kf = 64; Nf = 3;  KH = 2; q = i - 2432; }

    int lane = q & 31, t2 = q >> 5;
    int kh = t2 % KH, nt = t2 / KH;
    int g = lane >> 2, cp = lane & 3;
    int n = nt * 8 + g;

    auto pw = [&](int kk) -> float {
        return (kk < Kf) ? wfetch(W, Nf, n, kk, c0) : 0.f;
    };
    int k0 = 16 * (2 * kh) + 2 * cp;
    int k1 = 16 * (2 * kh + 1) + 2 * cp;
    uint4 v;
    v.x = h2pack(pw(k0),     pw(k0 + 1));
    v.y = h2pack(pw(k0 + 8), pw(k0 + 9));
    v.z = h2pack(pw(k1),     pw(k1 + 1));
    v.w = h2pack(pw(k1 + 8), pw(k1 + 9));
    wbuf[i] = v;
}

// ---------------- main kernel (M=32/warp, persistent, R8 liveness profile) ----------------

template <int KT, int NT>
__device__ __forceinline__ void layer_mma(const uint32_t (*aR)[4][4], const uint4* __restrict__ swL,
                                          int lane, float (*acc)[4]) {
    constexpr int KH = (KT + 1) / 2;
    constexpr int NG = (NT < 4) ? NT : 4;
#pragma unroll
    for (int i = 0; i < 2 * NT; i++)
#pragma unroll
        for (int qq = 0; qq < 4; qq++) acc[i][qq] = 0.f;

#pragma unroll
    for (int kh = 0; kh < KH; kh++) {
#pragma unroll
        for (int h = 0; h < NT / NG; h++) {
            uint4 wv[NG];
#pragma unroll
            for (int j = 0; j < NG; j++)
                wv[j] = swL[((h * NG + j) * KH + kh) * 32 + lane];
#pragma unroll
            for (int j = 0; j < NG; j++)
#pragma unroll
                for (int mt = 0; mt < 2; mt++)
                    mma16(acc[mt * NT + h * NG + j], aR[mt][2 * kh], wv[j].x, wv[j].y);
            if (2 * kh + 1 < KT) {
#pragma unroll
                for (int j = 0; j < NG; j++)
#pragma unroll
                    for (int mt = 0; mt < 2; mt++)
                        mma16(acc[mt * NT + h * NG + j], aR[mt][2 * kh + 1], wv[j].z, wv[j].w);
            }
        }
    }
}

__device__ __forceinline__ void cvt_relu8(const float (*acc)[4], uint32_t (*aR)[4][4]) {
#pragma unroll
    for (int mt = 0; mt < 2; mt++)
#pragma unroll
        for (int nt = 0; nt < 8; nt++) {
            int kt = nt >> 1, hi = (nt & 1) * 2;
            const float* dd = acc[mt * 8 + nt];
            aR[mt][kt][hi + 0] = h2relu(dd[0], dd[1]);
            aR[mt][kt][hi + 1] = h2relu(dd[2], dd[3]);
        }
}

// Load one warp's 32 rows of a [N,32] tensor into aR k-tiles 0,1 (fp16).
__device__ __forceinline__ void load_in(uint32_t (*aR)[4][4], const float* __restrict__ gsrc,
                                        int p0, int g, int cp) {
#pragma unroll
    for (int mt = 0; mt < 2; mt++)
#pragma unroll
        for (int kt = 0; kt < 2; kt++) {
            const float* ra = gsrc + (size_t)(p0 + mt * 16 + g) * 32 + 2 * cp + 16 * kt;
            const float* rb = ra + 8 * 32;
            float2 v0 = *(const float2*)(ra);
            float2 v1 = *(const float2*)(rb);
            float2 v2 = *(const float2*)(ra + 8);
            float2 v3 = *(const float2*)(rb + 8);
            aR[mt][kt][0] = h2pack(v0.x, v0.y);
            aR[mt][kt][1] = h2pack(v1.x, v1.y);
            aR[mt][kt][2] = h2pack(v2.x, v2.y);
            aR[mt][kt][3] = h2pack(v3.x, v3.y);
        }
}

__global__ __launch_bounds__(TPB, 2)
void RadianceFieldGrid_kernel(const float* __restrict__ x,
                              const float* __restrict__ din,
                              float* __restrict__ out, int N, int numTiles) {
    __shared__ uint4 sW[WU4];   // 39.9 KB

    const int t    = threadIdx.x;
    const int lane = t & 31;
    const int w    = t >> 5;
    const int g    = lane >> 2;
    const int cp   = lane & 3;

    // one-time weight copy; persistent CTA amortizes it over ~14 tiles
    for (int i = t; i < WU4; i += TPB) sW[i] = wbuf[i];
    __syncthreads();

    float* __restrict__ sigmaOut = out + (size_t)3 * N;

    uint32_t aR[2][4][4];
    float acc[16][4];

    for (int tile = blockIdx.x; tile < numTiles; tile += gridDim.x) {
        const int p0 = tile * 256 + w * 32;   // this warp's first point

        // ---- sigma net ----
        load_in(aR, x, p0, g, cp);
        layer_mma<2, 8>(aR, sW + OFF_S0, lane, acc);
        cvt_relu8(acc, aR);
        layer_mma<4, 8>(aR, sW + OFF_S1, lane, acc);
        cvt_relu8(acc, aR);
        layer_mma<4, 2>(aR, sW + OFF_S2, lane, acc);   // acc[mt*2+nt]

        // sigma = relu(col 0) -> out[3N + p]
        if (cp == 0) {
#pragma unroll
            for (int mt = 0; mt < 2; mt++) {
                sigmaOut[p0 + mt * 16 + g]     = fmaxf(acc[mt * 2][0], 0.f);
                sigmaOut[p0 + mt * 16 + g + 8] = fmaxf(acc[mt * 2][2], 0.f);
            }
        }

        // color A: k-tile 2 = relu(L2 D-frags); then d straight into k-tiles 0,1
        // (loaded HERE, at minimum register liveness -- only 8 acc regs live)
#pragma unroll
        for (int mt = 0; mt < 2; mt++) {
            const float* d0 = acc[mt * 2 + 0];
            const float* d1 = acc[mt * 2 + 1];
            aR[mt][2][0] = h2relu(d0[0], d0[1]);
            aR[mt][2][1] = h2relu(d0[2], d0[3]);
            aR[mt][2][2] = h2relu(d1[0], d1[1]);
            aR[mt][2][3] = h2relu(d1[2], d1[3]);
        }
        load_in(aR, din, p0, g, cp);   // writes aR[mt][0..1] directly

        // ---- color net ----
        layer_mma<3, 8>(aR, sW + OFF_C0, lane, acc);
        cvt_relu8(acc, aR);
        layer_mma<4, 8>(aR, sW + OFF_C1, lane, acc);
        cvt_relu8(acc, aR);
        layer_mma<4, 8>(aR, sW + OFF_C2, lane, acc);
        cvt_relu8(acc, aR);
        layer_mma<4, 1>(aR, sW + OFF_C3, lane, acc);   // acc[mt]

        // sigmoid + store color (cols 0..2)
#pragma unroll
        for (int mt = 0; mt < 2; mt++)
#pragma unroll
            for (int qq = 0; qq < 4; qq++) {
                int c = 2 * cp + (qq & 1);
                if (c < 3) {
                    int row = mt * 16 + g + 8 * (qq >> 1);
                    float v = acc[mt][qq];
                    out[(size_t)(p0 + row) * 3 + c] = 1.f / (1.f + __expf(-v));
                }
            }
    }
}

extern "C" void kernel_launch(void* const* d_in, const int* in_sizes, int n_in,
                              void* d_out, int out_size) {
    const float* x   = (const float*)d_in[0];
    const float* din = (const float*)d_in[1];
    const float* Ws0 = (const float*)d_in[2];
    const float* Ws1 = (const float*)d_in[3];
    const float* Ws2 = (const float*)d_in[4];
    const float* Wc0 = (const float*)d_in[5];
    const float* Wc1 = (const float*)d_in[6];
    const float* Wc2 = (const float*)d_in[7];
    const float* Wc3 = (const float*)d_in[8];
    float* out = (float*)d_out;

    int N = in_sizes[0] / 32;   // x is [N, 32]
    int numTiles = N / 256;     // 256 points per CTA-tile

    prep_kernel<<<(WU4 + 255) / 256, 256>>>(Ws0, Ws1, Ws2, Wc0, Wc1, Wc2, Wc3);
    RadianceFieldGrid_kernel<<<148 * 2, TPB>>>(x, din, out, N, numTiles);
}